// round 8
// baseline (speedup 1.0000x reference)
#include <cuda_runtime.h>
#include <math.h>

#define BB    512
#define LL    100
#define MM    10
#define DD    256
#define NASP  14
#define BT    4
#define NPOSBLK (BB/BT)         // 128
#define NNEGBLK (BB*MM)         // 5120

#define OFF_RS  0
#define OFF_ZS  (BB*DD)
#define OFF_ZN  (2*BB*DD)

__device__ __forceinline__ float blockReduce256(float v, float* sh8) {
    #pragma unroll
    for (int o = 16; o > 0; o >>= 1) v += __shfl_xor_sync(0xffffffffu, v, o);
    int w = threadIdx.x >> 5;
    if ((threadIdx.x & 31) == 0) sh8[w] = v;
    __syncthreads();
    float tot = sh8[0]+sh8[1]+sh8[2]+sh8[3]+sh8[4]+sh8[5]+sh8[6]+sh8[7];
    return tot;
}

// Sum of 100 gathered scalars (thread-owned column), 10-deep load batches.
// Each warp-instruction covers one 128B line (cross-LDG 1 wf/cyc rate).
__device__ __forceinline__ float gather100(const float* __restrict__ Ept,
                                           const int* __restrict__ offs)
{
    float a0 = 0.f, a1 = 0.f, a2 = 0.f, a3 = 0.f;
    #pragma unroll
    for (int j = 0; j < 10; j++) {
        const int* o = offs + j * 10;
        float v0 = Ept[o[0]], v1 = Ept[o[1]], v2 = Ept[o[2]], v3 = Ept[o[3]];
        float v4 = Ept[o[4]], v5 = Ept[o[5]], v6 = Ept[o[6]], v7 = Ept[o[7]];
        float v8 = Ept[o[8]], v9 = Ept[o[9]];
        a0 += v0 + v4; a1 += v1 + v5 + v8;
        a2 += v2 + v6 + v9; a3 += v3 + v7;
    }
    return (a0 + a1) + (a2 + a3);
}

// ---------------------------------------------------------------------------
// Unified kernel, 256 threads/block.
//   blocks [0, NPOSBLK):   full pos chain for BT batches (self-contained)
//   blocks [NPOSBLK, ...): z_n = l2norm(sum_l e)  (mean cancels under l2norm)
// ---------------------------------------------------------------------------
__global__ __launch_bounds__(256, 4) void k_all(
    const int* __restrict__ pos, const int* __restrict__ negs,
    const float* __restrict__ E,
    const float4* __restrict__ Mw4, const float* __restrict__ Mb,
    const float* __restrict__ Tw, const float4* __restrict__ lw4,
    const float* __restrict__ lb, float* __restrict__ out)
{
    __shared__ float sh8[8];
    const int t = threadIdx.x, blk = blockIdx.x;
    const int wid = t >> 5, lane = t & 31;
    const float* Ept = E + t;

    if (blk >= NPOSBLK) {
        // ---------------- negatives: z_n ----------------
        __shared__ int offs[LL];
        const int bm = blk - NPOSBLK;
        if (t < LL) offs[t] = negs[bm * LL + t] * DD;
        __syncthreads();

        float s = gather100(Ept, offs);
        float tot = blockReduce256(s * s, sh8);
        float inv = 1.f / fmaxf(sqrtf(tot), 1e-12f);
        out[OFF_ZN + bm * DD + t] = s * inv;
        return;
    }

    // ---------------- pos chain for batches [b0, b0+BT) ----------------
    __shared__ int   offsP[BT][LL];
    __shared__ float ysMy[BT][DD];     // ys in phases 1-2, then overlaid by My
    __shared__ float redf[8][DD];      // 8KB cross-warp reduce for attn
    __shared__ float zs[DD];
    __shared__ float lg[NASP];
    __shared__ float ps[NASP];
    const int b0 = blk * BT;

    if (t < LL) {
        #pragma unroll
        for (int i = 0; i < BT; i++)
            offsP[i][t] = pos[(b0 + i) * LL + t] * DD;
    }
    __syncthreads();

    // Phase 1: means -> ysMy[i][t]  (thread t owns column t; no reduction)
    #pragma unroll
    for (int i = 0; i < BT; i++)
        ysMy[i][t] = gather100(Ept, offsP[i]) * (1.f / LL);
    __syncthreads();

    // Phase 2: acc[i] = Mw row t . ys[i]; overlay My into ysMy
    {
        const float4* mr = Mw4 + t * 64;
        float acc[BT];
        #pragma unroll
        for (int i = 0; i < BT; i++) acc[i] = 0.f;
        #pragma unroll 4
        for (int d = 0; d < 64; d++) {
            float4 w = mr[d];
            #pragma unroll
            for (int i = 0; i < BT; i++) {
                acc[i] += w.x * ysMy[i][4*d]   + w.y * ysMy[i][4*d+1]
                        + w.z * ysMy[i][4*d+2] + w.w * ysMy[i][4*d+3];
            }
        }
        float bb = Mb[t];
        __syncthreads();
        #pragma unroll
        for (int i = 0; i < BT; i++) ysMy[i][t] = acc[i] + bb;
    }
    __syncthreads();

    // Phase 3: per-batch FUSED attention (scalar coalesced; row in regs for
    // both score and weighted accumulation) + aspect head.
    for (int i = 0; i < BT; i++) {
        const int b = b0 + i;
        float m[8];
        #pragma unroll
        for (int k = 0; k < 8; k++) m[k] = ysMy[i][lane + 32*k];

        float acc[8];
        #pragma unroll
        for (int k = 0; k < 8; k++) acc[k] = 0.f;

        // 2-token software pipeline per warp (tokens l0, l0+8)
        for (int l0 = wid; l0 < LL; l0 += 16) {
            const int l1 = l0 + 8;
            const bool has1 = (l1 < LL);
            const float* e0 = E + offsP[i][l0];
            const float* e1 = E + offsP[i][has1 ? l1 : l0];
            float v[8], u[8];
            #pragma unroll
            for (int k = 0; k < 8; k++) v[k] = e0[lane + 32*k];
            #pragma unroll
            for (int k = 0; k < 8; k++) u[k] = e1[lane + 32*k];

            float p0 = 0.f, p1 = 0.f;
            #pragma unroll
            for (int k = 0; k < 8; k++) { p0 += v[k]*m[k]; p1 += u[k]*m[k]; }
            #pragma unroll
            for (int o = 16; o > 0; o >>= 1) {
                p0 += __shfl_xor_sync(0xffffffffu, p0, o);
                p1 += __shfl_xor_sync(0xffffffffu, p1, o);
            }
            float w0 = expf(tanhf(p0));
            float w1 = has1 ? expf(tanhf(p1)) : 0.f;
            #pragma unroll
            for (int k = 0; k < 8; k++) acc[k] += w0*v[k] + w1*u[k];
        }

        // cross-warp reduce: warp wid contributes to columns lane+32k
        #pragma unroll
        for (int k = 0; k < 8; k++) redf[wid][lane + 32*k] = acc[k];
        __syncthreads();
        float s = redf[0][t];
        #pragma unroll
        for (int w = 1; w < 8; w++) s += redf[w][t];

        float tot = blockReduce256(s * s, sh8);
        float inv = 1.f / fmaxf(sqrtf(tot), 1e-12f);
        s *= inv;
        zs[t] = s;
        out[OFF_ZS + b * DD + t] = s;
        __syncthreads();

        // logits over 14 aspects (warp per aspect)
        for (int asp = wid; asp < NASP; asp += 8) {
            const float4* lr = lw4 + asp * 64;
            float4 v1 = lr[lane], v2 = lr[lane + 32];
            float4 z1 = ((const float4*)zs)[lane];
            float4 z2 = ((const float4*)zs)[lane + 32];
            float p = v1.x*z1.x + v1.y*z1.y + v1.z*z1.z + v1.w*z1.w
                    + v2.x*z2.x + v2.y*z2.y + v2.z*z2.z + v2.w*z2.w;
            #pragma unroll
            for (int o = 16; o > 0; o >>= 1) p += __shfl_xor_sync(0xffffffffu, p, o);
            if (lane == 0) lg[asp] = p + lb[asp];
        }
        __syncthreads();

        if (t == 0) {
            float mx = -1e30f;
            #pragma unroll
            for (int aa = 0; aa < NASP; aa++) mx = fmaxf(mx, lg[aa]);
            float sum = 0.f;
            #pragma unroll
            for (int aa = 0; aa < NASP; aa++) { float e = expf(lg[aa]-mx); ps[aa] = e; sum += e; }
            float invs = 1.f / sum;
            #pragma unroll
            for (int aa = 0; aa < NASP; aa++) ps[aa] *= invs;
        }
        __syncthreads();

        {
            float rr = 0.f;
            #pragma unroll
            for (int aa = 0; aa < NASP; aa++) rr += ps[aa] * Tw[aa * DD + t];
            float tot2 = blockReduce256(rr * rr, sh8);
            float nrm = fmaxf(sqrtf(tot2), 1e-12f);
            out[OFF_RS + b * DD + t] = rr / nrm;
        }
        __syncthreads();
    }
}

extern "C" void kernel_launch(void* const* d_in, const int* in_sizes, int n_in,
                              void* d_out, int out_size)
{
    const int*   pos  = (const int*)d_in[0];
    const int*   negs = (const int*)d_in[1];
    const float* E_w  = (const float*)d_in[2];
    const float* T_w  = (const float*)d_in[3];
    const float* M_w  = (const float*)d_in[4];
    const float* M_b  = (const float*)d_in[5];
    const float* lw   = (const float*)d_in[6];
    const float* lb   = (const float*)d_in[7];
    float* out = (float*)d_out;

    k_all<<<NPOSBLK + NNEGBLK, 256>>>(
        pos, negs, E_w,
        (const float4*)M_w, M_b,
        T_w, (const float4*)lw, lb, out);
}

// round 10
// speedup vs baseline: 1.0667x; 1.0667x over previous
#include <cuda_runtime.h>
#include <math.h>

#define BB    512
#define LL    100
#define MM    10
#define DD    256
#define NASP  14
#define BT    4
#define NPOSBLK (BB/BT)         // 128
#define NNEGBLK (BB*MM)         // 5120

#define OFF_RS  0
#define OFF_ZS  (BB*DD)
#define OFF_ZN  (2*BB*DD)

#define F4ADD(a, v) { a.x += v.x; a.y += v.y; a.z += v.z; a.w += v.w; }

__device__ __forceinline__ void f4fma(float4& a, float s, const float4& v) {
    a.x += s * v.x; a.y += s * v.y; a.z += s * v.z; a.w += s * v.w;
}

// Gather-sum of 25 rows (l = 4*i + r) with 8-deep load batching.
__device__ __forceinline__ float4 gather25(
    const float4* __restrict__ E4, const int* __restrict__ idx,
    int r, int c)
{
    float4 a0 = make_float4(0.f,0.f,0.f,0.f);
    float4 a1 = make_float4(0.f,0.f,0.f,0.f);
    #pragma unroll
    for (int j = 0; j < 3; j++) {
        const int i0 = j * 8;
        float4 v0 = E4[(size_t)idx[(i0+0)*4+r] * 64 + c];
        float4 v1 = E4[(size_t)idx[(i0+1)*4+r] * 64 + c];
        float4 v2 = E4[(size_t)idx[(i0+2)*4+r] * 64 + c];
        float4 v3 = E4[(size_t)idx[(i0+3)*4+r] * 64 + c];
        float4 v4 = E4[(size_t)idx[(i0+4)*4+r] * 64 + c];
        float4 v5 = E4[(size_t)idx[(i0+5)*4+r] * 64 + c];
        float4 v6 = E4[(size_t)idx[(i0+6)*4+r] * 64 + c];
        float4 v7 = E4[(size_t)idx[(i0+7)*4+r] * 64 + c];
        F4ADD(a0, v0); F4ADD(a1, v1); F4ADD(a0, v2); F4ADD(a1, v3);
        F4ADD(a0, v4); F4ADD(a1, v5); F4ADD(a0, v6); F4ADD(a1, v7);
    }
    float4 v = E4[(size_t)idx[24*4+r] * 64 + c];
    F4ADD(a0, v);
    F4ADD(a0, a1);
    return a0;
}

__device__ __forceinline__ float dot8(const float4& v1, const float4& v2,
                                      const float4& m1, const float4& m2)
{
    return v1.x*m1.x + v1.y*m1.y + v1.z*m1.z + v1.w*m1.w
         + v2.x*m2.x + v2.y*m2.y + v2.z*m2.z + v2.w*m2.w;
}

// ---------------------------------------------------------------------------
// Unified kernel, 256 threads/block, 5 CTAs/SM target.
//   blocks [0, NPOSBLK):   full pos chain for BT batches (self-contained)
//   blocks [NPOSBLK, ...): z_n = l2norm(sum_l e)  (mean cancels under l2norm)
// ---------------------------------------------------------------------------
__global__ __launch_bounds__(256, 5) void k_all(
    const int* __restrict__ pos, const int* __restrict__ negs,
    const float4* __restrict__ E4,
    const float4* __restrict__ Mw4, const float* __restrict__ Mb,
    const float4* __restrict__ Tw4, const float4* __restrict__ lw4,
    const float* __restrict__ lb, float* __restrict__ out)
{
    __shared__ float4 redAB[512];   // 8KB; first 256 entries double as the
                                    // phase-reduce buffer
    __shared__ float sh8[8];
    float4* red = redAB;
    const int t = threadIdx.x, blk = blockIdx.x;
    const int r = t >> 6, c = t & 63;
    const int wid = t >> 5, lane = t & 31;

    if (blk >= NPOSBLK) {
        // ---------------- negatives: z_n ----------------
        __shared__ int idx[LL];
        const int bm = blk - NPOSBLK;
        if (t < LL) idx[t] = negs[bm * LL + t];
        __syncthreads();

        float4 a = gather25(E4, idx, r, c);
        red[t] = a;
        __syncthreads();
        if (t < 64) {
            float4 s = red[t], p1 = red[t+64], p2 = red[t+128], p3 = red[t+192];
            s.x += p1.x+p2.x+p3.x; s.y += p1.y+p2.y+p3.y;
            s.z += p1.z+p2.z+p3.z; s.w += p1.w+p2.w+p3.w;
            red[t] = s;
            float ss = s.x*s.x + s.y*s.y + s.z*s.z + s.w*s.w;
            #pragma unroll
            for (int o = 16; o > 0; o >>= 1) ss += __shfl_xor_sync(0xffffffffu, ss, o);
            if (lane == 0) sh8[wid] = ss;
        }
        __syncthreads();
        if (t < 64) {
            float inv = 1.f / fmaxf(sqrtf(sh8[0] + sh8[1]), 1e-12f);
            float4 s = red[t];
            s.x *= inv; s.y *= inv; s.z *= inv; s.w *= inv;
            ((float4*)(out + OFF_ZN))[bm * 64 + t] = s;
        }
        return;
    }

    // ---------------- pos chain for batches [b0, b0+BT) ----------------
    __shared__ int   idxs[BT][LL];
    __shared__ float ysMy[BT][DD];     // ys in phases 1-2, then overlaid by My
    __shared__ float zs[DD];
    __shared__ float lg[NASP];
    __shared__ float ps[NASP];
    const int b0 = blk * BT;

    for (int i = 0; i < BT; i++)
        if (t < LL) idxs[i][t] = pos[(b0 + i) * LL + t];
    __syncthreads();

    // Phase 1: means -> ysMy[i][*]
    for (int i = 0; i < BT; i++) {
        float4 a = gather25(E4, idxs[i], r, c);
        red[t] = a;
        __syncthreads();
        if (t < 64) {
            float4 s = red[t], p1 = red[t+64], p2 = red[t+128], p3 = red[t+192];
            s.x = (s.x+p1.x+p2.x+p3.x) * (1.f/LL);
            s.y = (s.y+p1.y+p2.y+p3.y) * (1.f/LL);
            s.z = (s.z+p1.z+p2.z+p3.z) * (1.f/LL);
            s.w = (s.w+p1.w+p2.w+p3.w) * (1.f/LL);
            ((float4*)ysMy[i])[t] = s;
        }
        __syncthreads();
    }

    // Phase 2: acc[i] = Mw row t . ys[i]; overlay My into ysMy
    {
        const float4* mr = Mw4 + t * 64;
        float acc[BT];
        #pragma unroll
        for (int i = 0; i < BT; i++) acc[i] = 0.f;
        #pragma unroll 4
        for (int d = 0; d < 64; d++) {
            float4 w = mr[d];
            #pragma unroll
            for (int i = 0; i < BT; i++) {
                acc[i] += w.x * ysMy[i][4*d]   + w.y * ysMy[i][4*d+1]
                        + w.z * ysMy[i][4*d+2] + w.w * ysMy[i][4*d+3];
            }
        }
        float bb = Mb[t];
        __syncthreads();
        #pragma unroll
        for (int i = 0; i < BT; i++) ysMy[i][t] = acc[i] + bb;
    }
    __syncthreads();

    // Phase 3: per-batch FUSED attention (dot + weighted sum in one gather
    // pass; row stays in regs) + aspect head.
    for (int i = 0; i < BT; i++) {
        const int b = b0 + i;
        const float4 m1 = ((const float4*)ysMy[i])[lane];
        const float4 m2 = ((const float4*)ysMy[i])[lane + 32];

        float4 a1 = make_float4(0.f,0.f,0.f,0.f);
        float4 a2 = make_float4(0.f,0.f,0.f,0.f);

        // 2-token software pipeline per warp (tokens l0, l0+8)
        for (int l0 = wid; l0 < LL; l0 += 16) {
            const int l1 = l0 + 8;
            const bool has1 = (l1 < LL);
            const float4* e0 = E4 + (size_t)idxs[i][l0] * 64;
            const float4* e1 = E4 + (size_t)idxs[i][has1 ? l1 : l0] * 64;
            float4 v1 = e0[lane], v2 = e0[lane + 32];
            float4 u1 = e1[lane], u2 = e1[lane + 32];

            float p0 = dot8(v1, v2, m1, m2);
            float p1 = dot8(u1, u2, m1, m2);
            #pragma unroll
            for (int o = 16; o > 0; o >>= 1) {
                p0 += __shfl_xor_sync(0xffffffffu, p0, o);
                p1 += __shfl_xor_sync(0xffffffffu, p1, o);
            }
            float w0 = expf(tanhf(p0));
            float w1 = has1 ? expf(tanhf(p1)) : 0.f;
            f4fma(a1, w0, v1); f4fma(a2, w0, v2);
            f4fma(a1, w1, u1); f4fma(a2, w1, u2);
        }

        // cross-warp reduce: warp wid holds float4-cols lane (a1), 32+lane (a2)
        redAB[wid * 32 + lane] = a1;           // [0..255]
        redAB[256 + wid * 32 + lane] = a2;     // [256..511]
        __syncthreads();
        if (t < 64) {
            const int base = (t < 32) ? t : (256 + t - 32);
            float4 s = redAB[base];
            #pragma unroll
            for (int w = 1; w < 8; w++) {
                float4 p = redAB[base + w * 32];
                F4ADD(s, p);
            }
            red[t] = s;
            float ss = s.x*s.x + s.y*s.y + s.z*s.z + s.w*s.w;
            #pragma unroll
            for (int o = 16; o > 0; o >>= 1) ss += __shfl_xor_sync(0xffffffffu, ss, o);
            if (lane == 0) sh8[wid] = ss;
        }
        __syncthreads();
        if (t < 64) {
            float inv = 1.f / fmaxf(sqrtf(sh8[0] + sh8[1]), 1e-12f);
            float4 s = red[t];
            s.x *= inv; s.y *= inv; s.z *= inv; s.w *= inv;
            ((float4*)zs)[t] = s;
            ((float4*)(out + OFF_ZS))[b * 64 + t] = s;
        }
        __syncthreads();

        // logits over 14 aspects (warp per aspect)
        for (int asp = wid; asp < NASP; asp += 8) {
            const float4* lr = lw4 + asp * 64;
            float4 v1 = lr[lane], v2 = lr[lane + 32];
            float4 z1 = ((const float4*)zs)[lane];
            float4 z2 = ((const float4*)zs)[lane + 32];
            float p = dot8(v1, v2, z1, z2);
            #pragma unroll
            for (int o = 16; o > 0; o >>= 1) p += __shfl_xor_sync(0xffffffffu, p, o);
            if (lane == 0) lg[asp] = p + lb[asp];
        }
        __syncthreads();

        if (t == 0) {
            float mx = -1e30f;
            #pragma unroll
            for (int aa = 0; aa < NASP; aa++) mx = fmaxf(mx, lg[aa]);
            float s = 0.f;
            #pragma unroll
            for (int aa = 0; aa < NASP; aa++) { float e = expf(lg[aa]-mx); ps[aa] = e; s += e; }
            float inv = 1.f / s;
            #pragma unroll
            for (int aa = 0; aa < NASP; aa++) ps[aa] *= inv;
        }
        __syncthreads();

        {
            float rr = 0.f;
            #pragma unroll
            for (int aa = 0; aa < NASP; aa++) rr += ps[aa] * ((const float*)Tw4)[aa * DD + t];
            float v2 = rr * rr;
            #pragma unroll
            for (int o = 16; o > 0; o >>= 1) v2 += __shfl_xor_sync(0xffffffffu, v2, o);
            if (lane == 0) sh8[wid] = v2;
            __syncthreads();
            float tot = sh8[0]+sh8[1]+sh8[2]+sh8[3]+sh8[4]+sh8[5]+sh8[6]+sh8[7];
            float nrm = fmaxf(sqrtf(tot), 1e-12f);
            out[OFF_RS + b * DD + t] = rr / nrm;
        }
        __syncthreads();
    }
}

extern "C" void kernel_launch(void* const* d_in, const int* in_sizes, int n_in,
                              void* d_out, int out_size)
{
    const int*   pos  = (const int*)d_in[0];
    const int*   negs = (const int*)d_in[1];
    const float* E_w  = (const float*)d_in[2];
    const float* T_w  = (const float*)d_in[3];
    const float* M_w  = (const float*)d_in[4];
    const float* M_b  = (const float*)d_in[5];
    const float* lw   = (const float*)d_in[6];
    const float* lb   = (const float*)d_in[7];
    float* out = (float*)d_out;

    k_all<<<NPOSBLK + NNEGBLK, 256>>>(
        pos, negs, (const float4*)E_w,
        (const float4*)M_w, M_b,
        (const float4*)T_w, (const float4*)lw, lb, out);
}